// round 1
// baseline (speedup 1.0000x reference)
#include <cuda_runtime.h>

// MovingAvgNorm: x (B=32, T=16384, D=80) fp32.
// For each (b,t,d): window over padded time indices [t, t+K) with reflect pad
// (K/2 left, K/2-1 right)  ==  original indices o in [t-50, t+49], reflected.
// m = mean(window), v = unbiased std(window); out = (x - m) / (v + 1e-12).
//
// Strategy: one thread per d-lane (80 lanes / block), each thread owns a
// TCHUNK-long t-range and maintains running s1/s2 with O(1) add/remove per
// step. Warp lanes map to consecutive d -> fully coalesced 128B transactions.
// Fresh window init per chunk bounds fp32 drift to ~1e-5 in var.

#define MAN_B 32
#define MAN_T 16384
#define MAN_D 80
#define MAN_K 100
#define MAN_TCHUNK 256

__device__ __forceinline__ int refl(int o) {
    // single reflection suffices (pad < T)
    if (o < 0) return -o;
    if (o >= MAN_T) return 2 * MAN_T - 2 - o;
    return o;
}

__global__ __launch_bounds__(MAN_D) void moving_avg_norm_kernel(
    const float* __restrict__ x, float* __restrict__ out)
{
    const int d = threadIdx.x;                       // 0..79
    const int chunks_per_b = MAN_T / MAN_TCHUNK;     // 64
    const int b = blockIdx.x / chunks_per_b;
    const int t0 = (blockIdx.x % chunks_per_b) * MAN_TCHUNK;

    const float* __restrict__ xb = x + (size_t)b * MAN_T * MAN_D + d;
    float* __restrict__ ob = out + (size_t)b * MAN_T * MAN_D + d;

    const float inv_k  = 1.0f / MAN_K;
    const float inv_k1 = 1.0f / (MAN_K - 1);

    float s1 = 0.0f, s2 = 0.0f;

    // Initialize window for t = t0: o in [t0-50, t0+49]
    #pragma unroll 4
    for (int o = t0 - MAN_K / 2; o < t0 + MAN_K / 2; ++o) {
        int oo = refl(o);
        float v = __ldg(xb + (size_t)oo * MAN_D);
        s1 += v;
        s2 += v * v;
    }

    #pragma unroll 4
    for (int t = t0; t < t0 + MAN_TCHUNK; ++t) {
        float xc = __ldg(xb + (size_t)t * MAN_D);    // center (L1 hit: inside window)
        float m   = s1 * inv_k;
        float var = (s2 - s1 * s1 * inv_k) * inv_k1;
        float sd  = sqrtf(fmaxf(var, 0.0f));
        ob[(size_t)t * MAN_D] = (xc - m) / (sd + 1e-12f);

        // slide window: t -> t+1 adds o=t+50, removes o=t-50
        int oa = t + MAN_K / 2;
        oa = (oa >= MAN_T) ? (2 * MAN_T - 2 - oa) : oa;
        int orm = t - MAN_K / 2;
        orm = (orm < 0) ? -orm : orm;
        float va = __ldg(xb + (size_t)oa  * MAN_D);
        float vr = __ldg(xb + (size_t)orm * MAN_D);
        s1 += va - vr;
        s2 += va * va - vr * vr;
    }
}

extern "C" void kernel_launch(void* const* d_in, const int* in_sizes, int n_in,
                              void* d_out, int out_size)
{
    const float* x = (const float*)d_in[0];
    float* out = (float*)d_out;
    (void)in_sizes; (void)n_in; (void)out_size;

    const int grid = MAN_B * (MAN_T / MAN_TCHUNK);   // 32 * 64 = 2048 blocks
    moving_avg_norm_kernel<<<grid, MAN_D>>>(x, out);
}